// round 13
// baseline (speedup 1.0000x reference)
#include <cuda_runtime.h>
#include <cuda_bf16.h>
#include <math.h>

#define THR 0.005f
#define EPSI 1e-5f
#define NBATCH 4
#define NNODE 4096
#define NCH 64
#define SP 136   // padded bf16 row stride (272B) -> conflict-free ldmatrix

typedef unsigned long long ull;
typedef unsigned int uint;

// ---------------- device scratch ----------------
__device__ __align__(16) float g_xt[NBATCH * NNODE * NCH];     // x transposed [b][n][c]
__device__ __align__(16) float g_snorm[NBATCH * NNODE];
__device__ __align__(16) float g_dinv[NBATCH * NNODE];
__device__ __align__(16) unsigned g_adjT[NBATCH * 128 * NNODE];       // bits [b][word_m][n]
// bf16 split, node-major INTERLEAVED: [b][n][2c]=hi(x_c), [2c+1]=lo(x_c)
__device__ __align__(16) unsigned short g_xs [NBATCH * NNODE * 128];
__device__ __align__(16) unsigned short g_xs2[NBATCH * NNODE * 128];
// 3-way bf16 split planes, channel-major: [b][plane*64 + c][n], planes h,m,l
__device__ __align__(16) unsigned short g_xsp[NBATCH * 192 * NNODE];

// ---------------- helpers ----------------
__device__ __forceinline__ void fma2(ull& d, ull a, ull b) {
    asm("fma.rn.f32x2 %0, %1, %2, %0;" : "+l"(d) : "l"(a), "l"(b));
}
__device__ __forceinline__ ull pack2(float x) {
    ull r; asm("mov.b64 %0, {%1, %1};" : "=l"(r) : "f"(x)); return r;
}
union F2U { ull u; float2 f; };

__device__ __forceinline__ uint bfpair(uint u) {
    return ((u & 1u) ? 0x3F80u : 0u) | ((u & 2u) ? 0x3F800000u : 0u);
}

#define MMA_BF16(c, a0_, a1_, a2_, a3_, b0_, b1_) \
    asm volatile("mma.sync.aligned.m16n8k16.row.col.f32.bf16.bf16.f32 " \
        "{%0,%1,%2,%3},{%4,%5,%6,%7},{%8,%9},{%0,%1,%2,%3};" \
        : "+f"((c)[0]), "+f"((c)[1]), "+f"((c)[2]), "+f"((c)[3]) \
        : "r"(a0_), "r"(a1_), "r"(a2_), "r"(a3_), "r"(b0_), "r"(b1_))

// ---------------- prep: transpose + node norms + 3-way bf16 split ----------------
__global__ void __launch_bounds__(256) k_prep(const float* __restrict__ x) {
    __shared__ float xs2[64][65];   // [node][channel]
    int b = blockIdx.y, n0 = blockIdx.x * 64;
    int t = threadIdx.x;
    int c = t >> 2, seg = t & 3;
    {
        const float* xp = x + (size_t)(b * 64 + c) * NNODE + n0 + seg * 16;
        #pragma unroll
        for (int j = 0; j < 16; j++) xs2[seg * 16 + j][c] = xp[j];
    }
    __syncthreads();

    if (t < 64) {
        float s = 0.f;
        #pragma unroll
        for (int cc = 0; cc < 64; cc++) { float v = xs2[t][cc]; s += v * v; }
        g_snorm[b * NNODE + n0 + t] = sqrtf(s);
    }

    {
        int node = t >> 2, q = t & 3;
        float* op = g_xt + (size_t)(b * NNODE + n0 + node) * 64 + q * 16;
        #pragma unroll
        for (int j4 = 0; j4 < 4; j4++) {
            float4 v;
            v.x = xs2[node][q * 16 + j4 * 4 + 0];
            v.y = xs2[node][q * 16 + j4 * 4 + 1];
            v.z = xs2[node][q * 16 + j4 * 4 + 2];
            v.w = xs2[node][q * 16 + j4 * 4 + 3];
            *(float4*)(op + j4 * 4) = v;
        }
    }

    {
        unsigned short hb[16], mb[16], lb[16];
        #pragma unroll
        for (int j = 0; j < 16; j++) {
            float v = xs2[seg * 16 + j][c];
            __nv_bfloat16 h = __float2bfloat16_rn(v);
            float r1 = v - __bfloat162float(h);
            __nv_bfloat16 m = __float2bfloat16_rn(r1);
            __nv_bfloat16 l = __float2bfloat16_rn(r1 - __bfloat162float(m));
            hb[j] = *(unsigned short*)&h;
            mb[j] = *(unsigned short*)&m;
            lb[j] = *(unsigned short*)&l;
        }
        unsigned short* op = g_xsp + ((size_t)b * 192 + c) * NNODE + n0 + seg * 16;
        const size_t PL = (size_t)64 * NNODE;
        #pragma unroll
        for (int j4 = 0; j4 < 4; j4++) {
            *(ushort4*)(op + j4 * 4)          = *(ushort4*)&hb[j4 * 4];
            *(ushort4*)(op + PL + j4 * 4)     = *(ushort4*)&mb[j4 * 4];
            *(ushort4*)(op + 2 * PL + j4 * 4) = *(ushort4*)&lb[j4 * 4];
        }
    }
}

// ---------------- Gram via bf16 mma, PAIR-stacked split (virtual K=256) -------
__global__ void __launch_bounds__(256) k_gram() {
    __shared__ __align__(16) unsigned short As[2][32][SP];
    __shared__ __align__(16) unsigned short Bs[2][32][SP];
    __shared__ float sns[128], sms[128];

    int b = blockIdx.y;
    int xid = blockIdx.x;
    int bj = (int)((sqrtf(8.f * xid + 1.f) - 1.f) * 0.5f);
    while ((bj + 1) * (bj + 2) / 2 <= xid) bj++;
    while (bj * (bj + 1) / 2 > xid) bj--;
    int bi = xid - bj * (bj + 1) / 2;
    int n0 = bi * 128, m0 = bj * 128;

    int t = threadIdx.x, warp = t >> 5, lane = t & 31;
    int wn = warp >> 1, wm = warp & 1;

    if (t < 128) sns[t] = g_snorm[b * NNODE + n0 + t];
    else         sms[t - 128] = g_snorm[b * NNODE + m0 + (t - 128)];

    const unsigned short* xp = g_xsp + (size_t)b * 192 * NNODE;
    int seg = t & 15, kr0 = t >> 4;

    uint sa = (uint)__cvta_generic_to_shared(&As[0][0][0]);
    uint sb = (uint)__cvta_generic_to_shared(&Bs[0][0][0]);
    const uint BUFB = 32 * SP * 2;

    #define STAGE(kc, buf) do { \
        int p_ = (kc) >> 1; \
        int ka_ = (p_ & 1) * 64 + ((kc) & 1) * 32; \
        int kb_ = ((p_ >> 1) & 1) * 64 + ((kc) & 1) * 32; \
        uint da = sa + (buf) * BUFB; uint db = sb + (buf) * BUFB; \
        const unsigned short* a0_ = xp + (size_t)(ka_ + kr0) * NNODE + n0; \
        const unsigned short* a1_ = xp + (size_t)(ka_ + kr0 + 16) * NNODE + n0; \
        const unsigned short* b0_ = xp + (size_t)(kb_ + kr0) * NNODE + m0; \
        const unsigned short* b1_ = xp + (size_t)(kb_ + kr0 + 16) * NNODE + m0; \
        asm volatile("cp.async.ca.shared.global [%0], [%1], 16;" \
            :: "r"(da + (uint)(kr0 * SP + seg * 8) * 2),        "l"(a0_ + seg * 8)); \
        asm volatile("cp.async.ca.shared.global [%0], [%1], 16;" \
            :: "r"(da + (uint)((kr0 + 16) * SP + seg * 8) * 2), "l"(a1_ + seg * 8)); \
        asm volatile("cp.async.ca.shared.global [%0], [%1], 16;" \
            :: "r"(db + (uint)(kr0 * SP + seg * 8) * 2),        "l"(b0_ + seg * 8)); \
        asm volatile("cp.async.ca.shared.global [%0], [%1], 16;" \
            :: "r"(db + (uint)((kr0 + 16) * SP + seg * 8) * 2), "l"(b1_ + seg * 8)); \
        asm volatile("cp.async.commit_group;"); \
    } while (0)

    float cc[2][8][4];
    #pragma unroll
    for (int t2 = 0; t2 < 2; t2++)
        #pragma unroll
        for (int j = 0; j < 8; j++)
            #pragma unroll
            for (int q = 0; q < 4; q++) cc[t2][j][q] = 0.f;

    STAGE(0, 0);
    STAGE(1, 1);

    int krl = (lane & 7) + ((lane >> 3) & 1) * 8;
    int chalf = (lane >> 4) * 8;

    for (int kc = 0; kc < 8; kc++) {
        if (kc < 7) asm volatile("cp.async.wait_group 1;" ::: "memory");
        else        asm volatile("cp.async.wait_group 0;" ::: "memory");
        __syncthreads();
        int buf = kc & 1;
        uint ab = sa + buf * BUFB;
        uint bb = sb + buf * BUFB;
        #pragma unroll
        for (int ks = 0; ks < 2; ks++) {
            int kr = ks * 16 + krl;
            uint a[2][4];
            #pragma unroll
            for (int t2 = 0; t2 < 2; t2++) {
                uint addr = ab + (uint)(kr * SP + wn * 32 + t2 * 16 + chalf) * 2;
                asm volatile(
                    "ldmatrix.sync.aligned.m8n8.x4.trans.shared.b16 {%0,%1,%2,%3}, [%4];"
                    : "=r"(a[t2][0]), "=r"(a[t2][1]), "=r"(a[t2][2]), "=r"(a[t2][3])
                    : "r"(addr));
            }
            #pragma unroll
            for (int mg = 0; mg < 4; mg++) {
                uint r0, r1, r2, r3;
                uint addr = bb + (uint)(kr * SP + wm * 64 + mg * 16 + chalf) * 2;
                asm volatile(
                    "ldmatrix.sync.aligned.m8n8.x4.trans.shared.b16 {%0,%1,%2,%3}, [%4];"
                    : "=r"(r0), "=r"(r1), "=r"(r2), "=r"(r3)
                    : "r"(addr));
                #pragma unroll
                for (int t2 = 0; t2 < 2; t2++) {
                    MMA_BF16(cc[t2][2 * mg],     a[t2][0], a[t2][2], a[t2][1], a[t2][3], r0, r1);
                    MMA_BF16(cc[t2][2 * mg + 1], a[t2][0], a[t2][2], a[t2][1], a[t2][3], r2, r3);
                }
            }
        }
        __syncthreads();
        if (kc + 2 < 8) STAGE(kc + 2, buf);
    }

    int q = lane & 3, gid = lane >> 2;
    uint cb[2][2];
    #pragma unroll
    for (int t2 = 0; t2 < 2; t2++) {
        #pragma unroll
        for (int rh = 0; rh < 2; rh++) {
            int rl = wn * 32 + t2 * 16 + rh * 8 + gid;
            float sn = sns[rl];
            uint c = 0;
            #pragma unroll
            for (int j = 0; j < 8; j++) {
                int ml = wm * 64 + j * 8 + 2 * q;
                uint c0 = (cc[t2][j][rh * 2]     > THR * (sn * sms[ml]))     ? 1u : 0u;
                uint c1 = (cc[t2][j][rh * 2 + 1] > THR * (sn * sms[ml + 1])) ? 1u : 0u;
                c |= (c0 << (2 * j)) | (c1 << (2 * j + 1));
            }
            cb[t2][rh] = c;
            uint w0 = 0, w1 = 0;
            #pragma unroll
            for (int j = 0; j < 4; j++) {
                w0 |= ((c >> (2 * j)) & 1u)     << (j * 8 + 2 * q);
                w0 |= ((c >> (2 * j + 1)) & 1u) << (j * 8 + 2 * q + 1);
                w1 |= ((c >> (2 * j + 8)) & 1u) << (j * 8 + 2 * q);
                w1 |= ((c >> (2 * j + 9)) & 1u) << (j * 8 + 2 * q + 1);
            }
            w0 |= __shfl_xor_sync(0xffffffffu, w0, 1);
            w0 |= __shfl_xor_sync(0xffffffffu, w0, 2);
            w1 |= __shfl_xor_sync(0xffffffffu, w1, 1);
            w1 |= __shfl_xor_sync(0xffffffffu, w1, 2);
            if (q == 0) {
                int gn = n0 + rl;
                g_adjT[((size_t)b * 128 + (m0 >> 5) + wm * 2)     * NNODE + gn] = w0;
                g_adjT[((size_t)b * 128 + (m0 >> 5) + wm * 2 + 1) * NNODE + gn] = w1;
            }
        }
    }
    if (bi != bj) {
        #pragma unroll
        for (int idx = 0; idx < 16; idx++) {
            uint v = ((cb[0][0] >> idx) & 1u) << gid
                   | ((cb[0][1] >> idx) & 1u) << (gid + 8)
                   | ((cb[1][0] >> idx) & 1u) << (gid + 16)
                   | ((cb[1][1] >> idx) & 1u) << (gid + 24);
            v |= __shfl_xor_sync(0xffffffffu, v, 4);
            v |= __shfl_xor_sync(0xffffffffu, v, 8);
            v |= __shfl_xor_sync(0xffffffffu, v, 16);
            if (gid == 0) {
                int mg = m0 + wm * 64 + (idx >> 1) * 8 + 2 * lane + (idx & 1);
                g_adjT[((size_t)b * 128 + (n0 >> 5) + wn) * NNODE + mg] = v;
            }
        }
    }
}

// ---------------- fused degree + dinv + layer0 split (interleaved) ----------------
__global__ void __launch_bounds__(128) k_degsplit() {
    __shared__ int sc[4][32];
    __shared__ float sdv[32];

    int i0 = blockIdx.x * 32;
    int t = threadIdx.x, q = t >> 5, lane = t & 31;
    int gi = i0 + lane;
    int b = gi >> 12, nl = gi & 4095;
    const unsigned* base = g_adjT + (size_t)b * 128 * NNODE + nl;
    int c = 0;
    #pragma unroll 8
    for (int j = 0; j < 32; j++)
        c += __popc(base[(size_t)(q * 32 + j) * NNODE]);
    sc[q][lane] = c;
    __syncthreads();
    if (t < 32) {
        int tot = sc[0][t] + sc[1][t] + sc[2][t] + sc[3][t];
        float d = 1.0f / sqrtf((float)tot);
        g_dinv[i0 + t] = d;
        sdv[t] = d;
    }
    __syncthreads();

    int node = i0 + (t >> 2);
    float d = sdv[t >> 2];
    const float4* src = (const float4*)(g_xt + (size_t)node * 64 + (t & 3) * 16);
    unsigned short* o = g_xs + (size_t)node * 128 + (t & 3) * 32;
    #pragma unroll
    for (int j = 0; j < 4; j++) {
        float4 v = src[j];
        v.x *= d; v.y *= d; v.z *= d; v.w *= d;
        __nv_bfloat16 h0 = __float2bfloat16_rn(v.x);
        __nv_bfloat16 h1 = __float2bfloat16_rn(v.y);
        __nv_bfloat16 h2 = __float2bfloat16_rn(v.z);
        __nv_bfloat16 h3 = __float2bfloat16_rn(v.w);
        __nv_bfloat16 l0 = __float2bfloat16_rn(v.x - __bfloat162float(h0));
        __nv_bfloat16 l1 = __float2bfloat16_rn(v.y - __bfloat162float(h1));
        __nv_bfloat16 l2 = __float2bfloat16_rn(v.z - __bfloat162float(h2));
        __nv_bfloat16 l3 = __float2bfloat16_rn(v.w - __bfloat162float(h3));
        ushort4 p0, p1;
        p0.x = *(unsigned short*)&h0; p0.y = *(unsigned short*)&l0;
        p0.z = *(unsigned short*)&h1; p0.w = *(unsigned short*)&l1;
        p1.x = *(unsigned short*)&h2; p1.y = *(unsigned short*)&l2;
        p1.z = *(unsigned short*)&h3; p1.w = *(unsigned short*)&l3;
        *(ushort4*)(o + j * 8)     = p0;
        *(ushort4*)(o + j * 8 + 4) = p1;
    }
}

// ---------------- fused diffusion mma + FC + instance-norm + relu ----------------
// Block 128 thr = 4 warps over 64 rows x 128 phys-f; warp = 32 rows x 64 phys-f
// (rsel = wr>>1, fsel = wr&1). Interleaved hi/lo layout -> intra-thread combine.
__global__ void __launch_bounds__(128) k_mm(int layer, float* __restrict__ out_final,
                                            const float* __restrict__ W) {
    __shared__ union {
        unsigned short bs[2][64][SP];
        struct { float lxs[64][68]; float ws[64][64]; } e;
    } SM;

    int b = blockIdx.y, n0 = blockIdx.x * 64;
    int t = threadIdx.x, wr = t >> 5, lane = t & 31;
    int g = lane >> 2, tq = lane & 3;
    int rl8 = (lane & 7) + ((lane >> 3) & 1) * 8;
    int rsel = wr >> 1, fsel = wr & 1;
    int fg = fsel * 64 + (lane >> 4) * 8;

    const unsigned short* xsrc = (layer == 0) ? g_xs : g_xs2;
    const unsigned short* xsb = xsrc + (size_t)b * NNODE * 128;
    const unsigned* adjb = g_adjT + (size_t)b * 128 * NNODE + (n0 + rsel * 32 + g);

    float cc[2][8][4];
    #pragma unroll
    for (int t2 = 0; t2 < 2; t2++)
        #pragma unroll
        for (int j = 0; j < 8; j++)
            #pragma unroll
            for (int q = 0; q < 4; q++) cc[t2][j][q] = 0.f;

    int srow = t >> 4, schk = t & 15;
    uint sb0 = (uint)__cvta_generic_to_shared(&SM.bs[0][0][0]);
    uint sb1 = (uint)__cvta_generic_to_shared(&SM.bs[1][0][0]);

    float4 pf[8];
    #pragma unroll
    for (int ps = 0; ps < 8; ps++)
        pf[ps] = *(const float4*)(xsb + (size_t)(srow + ps * 8) * 128 + schk * 8);
    #pragma unroll
    for (int ps = 0; ps < 8; ps++)
        *(float4*)&SM.bs[0][srow + ps * 8][schk * 8] = pf[ps];
    #pragma unroll
    for (int ps = 0; ps < 8; ps++)
        pf[ps] = *(const float4*)(xsb + (size_t)(64 + srow + ps * 8) * 128 + schk * 8);

    // adjacency words: index = t2*4 + rp*2 + wi (rp: +0/+8 row, wi: word 2c/2c+1)
    uint wcur[8], wnxt[8];
    #pragma unroll
    for (int t2 = 0; t2 < 2; t2++)
        #pragma unroll
        for (int rp = 0; rp < 2; rp++)
            #pragma unroll
            for (int wi = 0; wi < 2; wi++)
                wcur[t2 * 4 + rp * 2 + wi] =
                    adjb[(size_t)wi * NNODE + t2 * 16 + rp * 8];

    for (int c = 0; c < 64; c++) {
        __syncthreads();
        if (c + 1 < 64) {
            #pragma unroll
            for (int ps = 0; ps < 8; ps++)
                *(float4*)&SM.bs[(c + 1) & 1][srow + ps * 8][schk * 8] = pf[ps];
            if (c + 2 < 64) {
                #pragma unroll
                for (int ps = 0; ps < 8; ps++)
                    pf[ps] = *(const float4*)(xsb + (size_t)((c + 2) * 64 + srow + ps * 8) * 128 + schk * 8);
            }
            #pragma unroll
            for (int t2 = 0; t2 < 2; t2++)
                #pragma unroll
                for (int rp = 0; rp < 2; rp++)
                    #pragma unroll
                    for (int wi = 0; wi < 2; wi++)
                        wnxt[t2 * 4 + rp * 2 + wi] =
                            adjb[(size_t)(2 * (c + 1) + wi) * NNODE + t2 * 16 + rp * 8];
        }
        uint bb = (c & 1) ? sb1 : sb0;
        #pragma unroll
        for (int q = 0; q < 4; q++) {
            int wi = q >> 1;
            int s = ((q & 1) << 4) + 2 * tq;
            uint A0[2], A1[2], A2[2], A3[2];
            #pragma unroll
            for (int t2 = 0; t2 < 2; t2++) {
                uint wg  = wcur[t2 * 4 + wi];
                uint wg8 = wcur[t2 * 4 + 2 + wi];
                A0[t2] = bfpair((wg >> s) & 3u);
                A2[t2] = bfpair((wg >> (s + 8)) & 3u);
                A1[t2] = bfpair((wg8 >> s) & 3u);
                A3[t2] = bfpair((wg8 >> (s + 8)) & 3u);
            }
            #pragma unroll
            for (int p = 0; p < 4; p++) {
                uint r0, r1, r2, r3;
                uint baddr = bb + (uint)(((q * 16 + rl8) * SP + fg + p * 16) * 2);
                asm volatile(
                    "ldmatrix.sync.aligned.m8n8.x4.trans.shared.b16 {%0,%1,%2,%3}, [%4];"
                    : "=r"(r0), "=r"(r1), "=r"(r2), "=r"(r3)
                    : "r"(baddr));
                #pragma unroll
                for (int t2 = 0; t2 < 2; t2++) {
                    MMA_BF16(cc[t2][2 * p],     A0[t2], A1[t2], A2[t2], A3[t2], r0, r1);
                    MMA_BF16(cc[t2][2 * p + 1], A0[t2], A1[t2], A2[t2], A3[t2], r2, r3);
                }
            }
        }
        #pragma unroll
        for (int i = 0; i < 8; i++) wcur[i] = wnxt[i];
    }
    __syncthreads();

    // epilogue: hi+lo combine (intra-thread), scale by dinv_n, stage lx
    #pragma unroll
    for (int t2 = 0; t2 < 2; t2++) {
        int lr0 = rsel * 32 + t2 * 16 + g;
        float dn0 = g_dinv[b * NNODE + n0 + lr0];
        float dn1 = g_dinv[b * NNODE + n0 + lr0 + 8];
        #pragma unroll
        for (int j = 0; j < 8; j++) {
            int f = fsel * 32 + j * 4 + tq;
            SM.e.lxs[lr0][f]     = (cc[t2][j][0] + cc[t2][j][1]) * dn0;
            SM.e.lxs[lr0 + 8][f] = (cc[t2][j][2] + cc[t2][j][3]) * dn1;
        }
    }
    {
        int c2 = t >> 1, fh = (t & 1) * 32;
        #pragma unroll
        for (int j = 0; j < 8; j++)
            *(float4*)&SM.e.ws[c2][fh + j * 4] = *(const float4*)(W + c2 * 64 + fh + j * 4);
    }
    __syncthreads();

    int row = t >> 1, fh = (t & 1) * 32;
    ull h[16];
    #pragma unroll
    for (int j = 0; j < 16; j++) h[j] = 0ULL;
    #pragma unroll 8
    for (int c = 0; c < 64; c++) {
        ull a2 = pack2(SM.e.lxs[row][c]);
        const ulonglong2* w2 = (const ulonglong2*)&SM.e.ws[c][fh];
        #pragma unroll
        for (int j = 0; j < 4; j++) {
            ulonglong2 u0 = w2[2 * j];
            ulonglong2 u1 = w2[2 * j + 1];
            fma2(h[4 * j],     a2, u0.x);
            fma2(h[4 * j + 1], a2, u0.y);
            fma2(h[4 * j + 2], a2, u1.x);
            fma2(h[4 * j + 3], a2, u1.y);
        }
    }
    float hv[32];
    #pragma unroll
    for (int j = 0; j < 16; j++) { F2U u; u.u = h[j]; hv[2 * j] = u.f.x; hv[2 * j + 1] = u.f.y; }

    float sum = 0.f;
    #pragma unroll
    for (int j = 0; j < 32; j++) sum += hv[j];
    sum += __shfl_xor_sync(0xffffffffu, sum, 1);
    float mean = sum * (1.f / 64.f);
    float vq = 0.f;
    #pragma unroll
    for (int j = 0; j < 32; j++) { float d = hv[j] - mean; vq += d * d; }
    vq += __shfl_xor_sync(0xffffffffu, vq, 1);
    float inv = 1.0f / sqrtf(vq * (1.f / 64.f) + EPSI);

    int gnode = b * NNODE + n0 + row;
    if (layer == 0) {
        float d = g_dinv[gnode];
        unsigned short* o = g_xs2 + (size_t)gnode * 128 + 2 * fh;   // interleaved
        #pragma unroll
        for (int f4 = 0; f4 < 8; f4++) {
            float y0 = fmaxf((hv[f4 * 4 + 0] - mean) * inv, 0.f) * d;
            float y1 = fmaxf((hv[f4 * 4 + 1] - mean) * inv, 0.f) * d;
            float y2 = fmaxf((hv[f4 * 4 + 2] - mean) * inv, 0.f) * d;
            float y3 = fmaxf((hv[f4 * 4 + 3] - mean) * inv, 0.f) * d;
            __nv_bfloat16 h0 = __float2bfloat16_rn(y0);
            __nv_bfloat16 h1 = __float2bfloat16_rn(y1);
            __nv_bfloat16 h2 = __float2bfloat16_rn(y2);
            __nv_bfloat16 h3 = __float2bfloat16_rn(y3);
            __nv_bfloat16 l0 = __float2bfloat16_rn(y0 - __bfloat162float(h0));
            __nv_bfloat16 l1 = __float2bfloat16_rn(y1 - __bfloat162float(h1));
            __nv_bfloat16 l2 = __float2bfloat16_rn(y2 - __bfloat162float(h2));
            __nv_bfloat16 l3 = __float2bfloat16_rn(y3 - __bfloat162float(h3));
            ushort4 p0, p1;
            p0.x = *(unsigned short*)&h0; p0.y = *(unsigned short*)&l0;
            p0.z = *(unsigned short*)&h1; p0.w = *(unsigned short*)&l1;
            p1.x = *(unsigned short*)&h2; p1.y = *(unsigned short*)&l2;
            p1.z = *(unsigned short*)&h3; p1.w = *(unsigned short*)&l3;
            *(ushort4*)(o + f4 * 8)     = p0;
            *(ushort4*)(o + f4 * 8 + 4) = p1;
        }
    } else {
        float* op = out_final + (size_t)gnode * 64 + fh;
        #pragma unroll
        for (int f4 = 0; f4 < 8; f4++) {
            float4 ov;
            ov.x = fmaxf((hv[f4 * 4 + 0] - mean) * inv, 0.f);
            ov.y = fmaxf((hv[f4 * 4 + 1] - mean) * inv, 0.f);
            ov.z = fmaxf((hv[f4 * 4 + 2] - mean) * inv, 0.f);
            ov.w = fmaxf((hv[f4 * 4 + 3] - mean) * inv, 0.f);
            *(float4*)(op + f4 * 4) = ov;
        }
    }
}

// ---------------- launch ----------------
extern "C" void kernel_launch(void* const* d_in, const int* in_sizes, int n_in,
                              void* d_out, int out_size) {
    const float* x  = (const float*)d_in[0];
    const float* W0 = (const float*)d_in[1];
    const float* W1 = (const float*)d_in[2];
    float* out = (float*)d_out;

    k_prep<<<dim3(64, 4), 256>>>(x);
    k_gram<<<dim3(528, 4), 256>>>();
    k_degsplit<<<512, 128>>>();
    k_mm<<<dim3(64, 4), 128>>>(0, nullptr, W0);
    k_mm<<<dim3(64, 4), 128>>>(1, out, W1);
}